// round 16
// baseline (speedup 1.0000x reference)
#include <cuda_runtime.h>
#include <cuda_bf16.h>
#include <cstdint>
#include <math.h>

#define VOCAB  32000
#define EMBED  300
#define KA     320
#define HIDDEN 512
#define G4     2048
#define BATCH  256
#define SEQ    512
#define NOUT   7

// ---------------------------------------------------------------------------
// Device scratch
// ---------------------------------------------------------------------------
__device__ float g_gx[(size_t)SEQ * BATCH * G4];   // [s][b][gate*512+j]
__device__ __nv_bfloat16 g_hh[2][BATCH * HIDDEN];
__device__ __nv_bfloat16 g_hl[2][BATCH * HIDDEN];
__device__ __nv_bfloat16 g_Wp_hi[(size_t)HIDDEN * G4];   // [k][n'=j*4+gate]
__device__ __nv_bfloat16 g_Wp_lo[(size_t)HIDDEN * G4];
__device__ __nv_bfloat16 g_emb_hi[(size_t)VOCAB * KA];
__device__ __nv_bfloat16 g_emb_lo[(size_t)VOCAB * KA];
__device__ __nv_bfloat16 g_wih_hi[(size_t)KA * G4];
__device__ __nv_bfloat16 g_wih_lo[(size_t)KA * G4];
// 4 independent sub-group barriers (one per 64-batch tile), 128B padded
__device__ unsigned g_cnt4[4 * 32];
__device__ unsigned g_epoch4[4 * 32];

// ---------------------------------------------------------------------------
// Helpers
// ---------------------------------------------------------------------------
__device__ __forceinline__ float sigf(float x) {
    return 1.f / (1.f + expf(-x));
}
__device__ __forceinline__ uint32_t smem_u32(const void* p) {
    return (uint32_t)__cvta_generic_to_shared(p);
}
__device__ __forceinline__ void ldsm_x4(uint32_t* r, uint32_t a) {
    asm volatile("ldmatrix.sync.aligned.m8n8.x4.shared.b16 {%0,%1,%2,%3}, [%4];"
        : "=r"(r[0]), "=r"(r[1]), "=r"(r[2]), "=r"(r[3]) : "r"(a));
}
__device__ __forceinline__ void ldsm_x4_t(uint32_t* r, uint32_t a) {
    asm volatile("ldmatrix.sync.aligned.m8n8.x4.trans.shared.b16 {%0,%1,%2,%3}, [%4];"
        : "=r"(r[0]), "=r"(r[1]), "=r"(r[2]), "=r"(r[3]) : "r"(a));
}
__device__ __forceinline__ void mma_bf16(float* d, const uint32_t* a,
                                         uint32_t b0, uint32_t b1) {
    asm volatile(
        "mma.sync.aligned.m16n8k16.row.col.f32.bf16.bf16.f32 "
        "{%0,%1,%2,%3}, {%4,%5,%6,%7}, {%8,%9}, {%0,%1,%2,%3};"
        : "+f"(d[0]), "+f"(d[1]), "+f"(d[2]), "+f"(d[3])
        : "r"(a[0]), "r"(a[1]), "r"(a[2]), "r"(a[3]), "r"(b0), "r"(b1));
}
#define CP16(dst, src) \
    asm volatile("cp.async.cg.shared.global [%0], [%1], 16;" \
                 :: "r"(dst), "l"(src))
#define CP_COMMIT() asm volatile("cp.async.commit_group;")
#define CP_WAIT1()  asm volatile("cp.async.wait_group 1;")
#define CP_WAIT0()  asm volatile("cp.async.wait_group 0;")
#define FENCE_ACQREL_GPU() asm volatile("fence.acq_rel.gpu;" ::: "memory")

// ---------------------------------------------------------------------------
// Prep kernels
// ---------------------------------------------------------------------------
__global__ void k_prep_w(const float* __restrict__ W_hh) {
    int idx = blockIdx.x * 256 + threadIdx.x;    // = k*2048 + n'
    int k  = idx >> 11;
    int np = idx & 2047;
    int gate = np & 3, j = np >> 2;
    float w = W_hh[(size_t)(gate * HIDDEN + j) * HIDDEN + k];
    __nv_bfloat16 hi = __float2bfloat16(w);
    g_Wp_hi[idx] = hi;
    g_Wp_lo[idx] = __float2bfloat16(w - __bfloat162float(hi));
}

__global__ void k_prep_wih(const float* __restrict__ W_ih) {
    int idx = blockIdx.x * 256 + threadIdx.x;    // k*2048 + g
    int k = idx >> 11;
    int g = idx & 2047;
    float w = (k < EMBED) ? W_ih[(size_t)g * EMBED + k] : 0.f;
    __nv_bfloat16 hi = __float2bfloat16(w);
    g_wih_hi[idx] = hi;
    g_wih_lo[idx] = __float2bfloat16(w - __bfloat162float(hi));
}

__global__ void k_prep_emb(const float* __restrict__ emb) {
    size_t idx = (size_t)blockIdx.x * 256 + threadIdx.x;  // row*KA + col
    int col = (int)(idx % KA);
    int row = (int)(idx / KA);
    float v = (row != 0 && col < EMBED) ? emb[(size_t)row * EMBED + col] : 0.f;
    __nv_bfloat16 hi = __float2bfloat16(v);
    g_emb_hi[idx] = hi;
    g_emb_lo[idx] = __float2bfloat16(v - __bfloat162float(hi));
}

// ---------------------------------------------------------------------------
// Kernel A (MMA): fused embedding gather + input projection, split-bf16.
// (proven R9/R11, unchanged)
// ---------------------------------------------------------------------------
#define PITCH  72
#define AHSZ   (128 * PITCH)
#define BHSZ   (64 * PITCH)
#define BOFF   (2 * AHSZ)
#define ASTAGE (2 * AHSZ + 2 * BHSZ)
#define NCHA   5
#define SMEM_EMB (3 * ASTAGE * 2)

__global__ __launch_bounds__(512, 1) void k_embed_mma(
    const int* __restrict__ tokens, const float* __restrict__ b_ih)
{
    extern __shared__ __align__(16) __nv_bfloat16 smem[];
    __shared__ int tok_s[128];

    const int tid = threadIdx.x;
    const int n0  = blockIdx.x * 64;
    const int m0  = blockIdx.y * 128;

    if (tid < 128) {
        int r = m0 + tid;
        int s = r >> 8;
        int b = r & 255;
        tok_s[tid] = tokens[b * SEQ + s];
    }
    __syncthreads();

    const int ar   = tid >> 2;
    const int aseg = (tid & 3) * 2;
    const int br   = tid >> 3;
    const int bseg = tid & 7;

    auto issue = [&](int c) {
        __nv_bfloat16* st = smem + (c % 3) * ASTAGE;
        int k0 = c * 64;
        const size_t abase = (size_t)tok_s[ar] * KA + k0;
        #pragma unroll
        for (int t = 0; t < 2; t++) {
            int seg = aseg + t;
            uint32_t d = smem_u32(st + ar * PITCH + seg * 8);
            CP16(d,            g_emb_hi + abase + seg * 8);
            CP16(d + 2 * AHSZ, g_emb_lo + abase + seg * 8);
        }
        const size_t bbase = (size_t)(k0 + br) * G4 + n0 + bseg * 8;
        uint32_t d = smem_u32(st + BOFF + br * PITCH + bseg * 8);
        CP16(d,            g_wih_hi + bbase);
        CP16(d + 2 * BHSZ, g_wih_lo + bbase);
    };

    issue(0); CP_COMMIT();
    issue(1); CP_COMMIT();

    const int wid  = tid >> 5;
    const int lane = tid & 31;
    const int wm   = (wid & 7) * 16;
    const int wn   = (wid >> 3) * 32;

    const int a_row = wm + (lane & 15);
    const int a_co  = (lane >> 4) * 8;
    const int b_ro  = (lane & 15);

    float accm[4][4], acc1[4][4], acc2[4][4];
    #pragma unroll
    for (int nt = 0; nt < 4; nt++)
        #pragma unroll
        for (int i = 0; i < 4; i++) {
            accm[nt][i] = 0.f; acc1[nt][i] = 0.f; acc2[nt][i] = 0.f;
        }

    for (int c = 0; c < NCHA; c++) {
        CP_WAIT1();
        __syncthreads();
        if (c + 2 < NCHA) issue(c + 2);
        CP_COMMIT();

        const __nv_bfloat16* st = smem + (c % 3) * ASTAGE;
        const __nv_bfloat16* Ah = st;
        const __nv_bfloat16* Al = st + AHSZ;
        const __nv_bfloat16* Bh = st + BOFF;
        const __nv_bfloat16* Bl = st + BOFF + BHSZ;

        #pragma unroll
        for (int ks = 0; ks < 4; ks++) {
            uint32_t ahi[4], alo[4], bhi[8], blo[8];
            ldsm_x4(ahi, smem_u32(Ah + a_row * PITCH + ks * 16 + a_co));
            ldsm_x4(alo, smem_u32(Al + a_row * PITCH + ks * 16 + a_co));
            int kr = ks * 16 + b_ro;
            int bc0 = wn + (lane >> 4) * 8;
            ldsm_x4_t(bhi,     smem_u32(Bh + kr * PITCH + bc0));
            ldsm_x4_t(bhi + 4, smem_u32(Bh + kr * PITCH + bc0 + 16));
            ldsm_x4_t(blo,     smem_u32(Bl + kr * PITCH + bc0));
            ldsm_x4_t(blo + 4, smem_u32(Bl + kr * PITCH + bc0 + 16));
            #pragma unroll
            for (int nt = 0; nt < 4; nt++) {
                mma_bf16(accm[nt], ahi, bhi[nt * 2], bhi[nt * 2 + 1]);
                mma_bf16(acc1[nt], ahi, blo[nt * 2], blo[nt * 2 + 1]);
                mma_bf16(acc2[nt], alo, bhi[nt * 2], bhi[nt * 2 + 1]);
            }
        }
    }

    #pragma unroll
    for (int nt = 0; nt < 4; nt++) {
        int col = n0 + wn + nt * 8 + (lane & 3) * 2;
        float2 bias = *(const float2*)&b_ih[col];
        float c0 = accm[nt][0] + acc1[nt][0] + acc2[nt][0] + bias.x;
        float c1 = accm[nt][1] + acc1[nt][1] + acc2[nt][1] + bias.y;
        float c2 = accm[nt][2] + acc1[nt][2] + acc2[nt][2] + bias.x;
        float c3 = accm[nt][3] + acc1[nt][3] + acc2[nt][3] + bias.y;
        size_t r0 = (size_t)(m0 + wm + (lane >> 2));
        __stcg((float2*)&g_gx[r0 * G4 + col],       make_float2(c0, c1));
        __stcg((float2*)&g_gx[(r0 + 8) * G4 + col], make_float2(c2, c3));
    }
}

// ---------------------------------------------------------------------------
// Persistent LSTM kernel (split-bf16 mma.sync, W resident in SMEM).
// v7 = R14 with k-chunk 128 and a 2-stage ring: 4 chunk barriers per step
// instead of 8 (7 total vs 12) — targets barrier re-convergence cost.
// A tiles use pitch 136 (row stride 68 banks = 4 mod 32: LDSM conflict-free).
// ---------------------------------------------------------------------------
#define WSPLIT  (HIDDEN * PITCH)           // 36864 elems per W split
#define RING0   (2 * WSPLIT)               // 73728 elems
#define APITCH  136                        // A row pitch (k128 + 8 pad)
#define HT2     (64 * APITCH)              // 8704 elems per split per stage
#define HSTG    (2 * HT2)                  // 17408 elems per stage
#define NCHK    4                          // 512 / 128
#define SMEM_PERSIST ((RING0 + 2 * HSTG) * 2)   // 217,088 B

__global__ __launch_bounds__(512, 1) void k_lstm_persist(
    const float* __restrict__ b_hh)
{
    extern __shared__ __align__(16) __nv_bfloat16 smem[];
    float* Csm = (float*)(smem + RING0);   // aliases ring stage 0 (34.8 KB)

    const int tid = threadIdx.x;
    const int cta = blockIdx.x;
    const int n0  = (cta & 31) * 64;
    const int bt  = cta >> 5;            // b-group 0..3
    const int b0  = bt * 64;
    const int jt0 = n0 >> 2;

    unsigned* cntp   = &g_cnt4[bt * 32];
    unsigned* epochp = &g_epoch4[bt * 32];

    // ---- one-time W load ----
    #pragma unroll
    for (int x = 0; x < 8; x++) {
        int o   = tid + x * 512;
        int k   = o >> 3;
        int seg = (o & 7) * 8;
        uint32_t d = smem_u32(smem + k * PITCH + seg);
        CP16(d, g_Wp_hi + (size_t)k * G4 + n0 + seg);
        uint32_t d2 = smem_u32(smem + WSPLIT + k * PITCH + seg);
        CP16(d2, g_Wp_lo + (size_t)k * G4 + n0 + seg);
    }
    CP_COMMIT();

    float bh[2][4], creg[2];
    #pragma unroll
    for (int t = 0; t < 2; t++) {
        int idx = tid + t * 512;
        int jl  = idx & 15;
        int j   = jt0 + jl;
        creg[t] = 0.f;
        #pragma unroll
        for (int g = 0; g < 4; g++) bh[t][g] = b_hh[g * HIDDEN + j];
    }

    CP_WAIT0();
    __syncthreads();

    // h staging map: row = tid>>3 (0..63), 2 segs of 16B per split
    const int ld_row = tid >> 3;
    const int ld_sub = tid & 7;

    const int wid  = tid >> 5;
    const int lane = tid & 31;
    const int wb   = (wid & 3) * 16;
    const int wn   = (wid >> 2) * 16;
    const int a_row = wb + (lane & 15);
    const int a_co  = (lane >> 4) * 8;
    const int b_ro  = (lane & 15);
    const int b_co  = wn + (lane >> 4) * 8;

    for (int s = 0; s < SEQ; s++) {
        const __nv_bfloat16* __restrict__ hhi = g_hh[s & 1];
        const __nv_bfloat16* __restrict__ hlo = g_hl[s & 1];
        __nv_bfloat16* __restrict__ ohh = g_hh[(s & 1) ^ 1];
        __nv_bfloat16* __restrict__ ohl = g_hl[(s & 1) ^ 1];

        // ---- gx prefetch into REGISTERS (hidden behind the whole GEMM) ----
        float gq[2][4];
        #pragma unroll
        for (int t = 0; t < 2; t++) {
            int idx = tid + t * 512;
            int jl = idx & 15, bl = idx >> 4;
            const float* gp = g_gx +
                ((size_t)s * BATCH + b0 + bl) * G4 + jt0 + jl;
            #pragma unroll
            for (int g = 0; g < 4; g++) gq[t][g] = __ldg(gp + g * HIDDEN);
        }

        // k128 chunk loader: 64 rows x 16 segs(16B) per split
        auto issueA = [&](int c) {
            __nv_bfloat16* st = smem + RING0 + (c & 1) * HSTG;
            const size_t base =
                (size_t)(b0 + ld_row) * HIDDEN + c * 128;
            #pragma unroll
            for (int t = 0; t < 2; t++) {
                int seg = ld_sub * 2 + t;          // 0..15
                uint32_t d = smem_u32(st + ld_row * APITCH + seg * 8);
                CP16(d,               hhi + base + seg * 8);
                CP16(d + 2 * HT2,     hlo + base + seg * 8);
            }
        };

        issueA(0); CP_COMMIT();

        float accm[2][4], acc1[2][4], acc2[2][4];
        #pragma unroll
        for (int nq = 0; nq < 2; nq++)
            #pragma unroll
            for (int i = 0; i < 4; i++) {
                accm[nq][i] = 0.f; acc1[nq][i] = 0.f; acc2[nq][i] = 0.f;
            }

        for (int c = 0; c < NCHK; c++) {
            CP_WAIT0();          // chunk c arrived (only outstanding group)
            __syncthreads();     // stage (c+1)&1 reads (chunk c-1) all done
            if (c + 1 < NCHK) { issueA(c + 1); CP_COMMIT(); }

            const __nv_bfloat16* Ah = smem + RING0 + (c & 1) * HSTG;
            const __nv_bfloat16* Al = Ah + HT2;

            #pragma unroll
            for (int ks = 0; ks < 8; ks++) {
                uint32_t ahi[4], alo[4], bhi[4], blo[4];
                ldsm_x4(ahi, smem_u32(Ah + a_row * APITCH + ks * 16 + a_co));
                ldsm_x4(alo, smem_u32(Al + a_row * APITCH + ks * 16 + a_co));
                int krow = c * 128 + ks * 16 + b_ro;
                ldsm_x4_t(bhi, smem_u32(smem + krow * PITCH + b_co));
                ldsm_x4_t(blo, smem_u32(smem + WSPLIT + krow * PITCH + b_co));
                #pragma unroll
                for (int nq = 0; nq < 2; nq++) {
                    mma_bf16(accm[nq], ahi, bhi[nq * 2], bhi[nq * 2 + 1]);
                    mma_bf16(acc1[nq], ahi, blo[nq * 2], blo[nq * 2 + 1]);
                    mma_bf16(acc2[nq], alo, bhi[nq * 2], bhi[nq * 2 + 1]);
                }
            }
        }

        #pragma unroll
        for (int nq = 0; nq < 2; nq++)
            #pragma unroll
            for (int i = 0; i < 4; i++)
                accm[nq][i] += acc1[nq][i] + acc2[nq][i];

        // stage C into SMEM (aliases ring stage 0: last read during chunk 2;
        // every warp passed the chunk-3 entry barrier after those reads, and
        // no cp.async targets stage 0 afterwards).  Disjoint 16x16 per warp.
        #pragma unroll
        for (int nq = 0; nq < 2; nq++) {
            int r0  = wb + (lane >> 2);
            int col = wn + nq * 8 + (lane & 3) * 2;
            *(float2*)&Csm[r0 * 68 + col] =
                make_float2(accm[nq][0], accm[nq][1]);
            *(float2*)&Csm[(r0 + 8) * 68 + col] =
                make_float2(accm[nq][2], accm[nq][3]);
        }
        __syncthreads();

        #pragma unroll
        for (int t = 0; t < 2; t++) {
            int idx = tid + t * 512;
            int jl = idx & 15, bl = idx >> 4;
            int b = b0 + bl, j = jt0 + jl;
            float4 cq = *(const float4*)&Csm[bl * 68 + jl * 4];  // i,f,g,o
            float gi = cq.x + gq[t][0] + bh[t][0];
            float gf = cq.y + gq[t][1] + bh[t][1];
            float gg = cq.z + gq[t][2] + bh[t][2];
            float go = cq.w + gq[t][3] + bh[t][3];
            float ig = sigf(gi), fg = sigf(gf);
            float gv = tanhf(gg), og = sigf(go);
            float cn = fg * creg[t] + ig * gv;
            creg[t] = cn;
            float hn = og * tanhf(cn);
            int ci = b * HIDDEN + j;
            __nv_bfloat16 hi = __float2bfloat16(hn);
            ohh[ci] = hi;
            ohl[ci] = __float2bfloat16(hn - __bfloat162float(hi));
        }

        // ---- sub-group epoch barrier (32 CTAs sharing this b-group) ----
        __syncthreads();
        if (tid == 0) {
            FENCE_ACQREL_GPU();
            unsigned a = atomicAdd(cntp, 1u);
            if (a == 31u) {
                *cntp = 0u;
                FENCE_ACQREL_GPU();
                *(volatile unsigned*)epochp = (unsigned)(s + 1);
            } else {
                while (*(volatile unsigned*)epochp < (unsigned)(s + 1)) { }
                FENCE_ACQREL_GPU();
            }
        }
        __syncthreads();
    }
}

// ---------------------------------------------------------------------------
// Init
// ---------------------------------------------------------------------------
__global__ void k_init() {
    int i = blockIdx.x * blockDim.x + threadIdx.x;
    if (i < BATCH * HIDDEN) {
        g_hh[0][i] = __float2bfloat16(0.f);
        g_hl[0][i] = __float2bfloat16(0.f);
    }
    if (i < 4 * 32) { g_cnt4[i] = 0u; g_epoch4[i] = 0u; }
}

// ---------------------------------------------------------------------------
// Kernel C: logits = h_T @ W_fc^T + b_fc
// ---------------------------------------------------------------------------
__global__ __launch_bounds__(128) void k_fc(
    const float* __restrict__ W_fc, const float* __restrict__ b_fc,
    float* __restrict__ out)
{
    const int b   = blockIdx.x;
    const int tid = threadIdx.x;

    float p[NOUT];
    #pragma unroll
    for (int o = 0; o < NOUT; o++) p[o] = 0.f;

    for (int jj = tid; jj < HIDDEN; jj += 128) {
        float hv = __bfloat162float(g_hh[0][b * HIDDEN + jj]) +
                   __bfloat162float(g_hl[0][b * HIDDEN + jj]);
        #pragma unroll
        for (int o = 0; o < NOUT; o++) p[o] += hv * W_fc[o * HIDDEN + jj];
    }

    __shared__ float redm[NOUT][128];
    #pragma unroll
    for (int o = 0; o < NOUT; o++) redm[o][tid] = p[o];
    __syncthreads();
    for (int st = 64; st > 0; st >>= 1) {
        if (tid < st) {
            #pragma unroll
            for (int o = 0; o < NOUT; o++) redm[o][tid] += redm[o][tid + st];
        }
        __syncthreads();
    }
    if (tid < NOUT) out[b * NOUT + tid] = redm[tid][0] + b_fc[tid];
}

// ---------------------------------------------------------------------------
// Launch
// ---------------------------------------------------------------------------
extern "C" void kernel_launch(void* const* d_in, const int* in_sizes, int n_in,
                              void* d_out, int out_size)
{
    const int*   tokens = (const int*)  d_in[0];
    const float* emb    = (const float*)d_in[1];
    const float* W_ih   = (const float*)d_in[2];
    const float* b_ih   = (const float*)d_in[3];
    const float* W_hh   = (const float*)d_in[4];
    const float* b_hh   = (const float*)d_in[5];
    const float* W_fc   = (const float*)d_in[6];
    const float* b_fc   = (const float*)d_in[7];
    float* out = (float*)d_out;

    static bool attr_set = false;
    if (!attr_set) {
        cudaFuncSetAttribute(k_lstm_persist,
                             cudaFuncAttributeMaxDynamicSharedMemorySize,
                             SMEM_PERSIST);
        cudaFuncSetAttribute(k_embed_mma,
                             cudaFuncAttributeMaxDynamicSharedMemorySize,
                             SMEM_EMB);
        attr_set = true;
    }

    k_init<<<(BATCH * HIDDEN + 255) / 256, 256>>>();
    k_prep_w<<<(HIDDEN * G4) / 256, 256>>>(W_hh);
    k_prep_wih<<<(KA * G4) / 256, 256>>>(W_ih);
    k_prep_emb<<<((size_t)VOCAB * KA) / 256, 256>>>(emb);

    dim3 gE(G4 / 64, (BATCH * SEQ) / 128);   // (32, 1024)
    k_embed_mma<<<gE, 512, SMEM_EMB>>>(tokens, b_ih);

    k_lstm_persist<<<128, 512, SMEM_PERSIST>>>(b_hh);

    k_fc<<<BATCH, 128>>>(W_fc, b_fc, out);
}